// round 9
// baseline (speedup 1.0000x reference)
#include <cuda_runtime.h>
#include <cstdint>

// Problem constants
constexpr int NN   = 50000;   // nodes
constexpr int NE   = 800000;  // edges
constexpr int FIN  = 128;
constexpr int FHID = 256;
constexpr int FOUT = 128;
constexpr int NB   = (NN + 1023) / 1024;   // scan blocks = 49

// ---------------- scratch (__device__ globals; referenced ONLY in device code)
__device__ __align__(16) int   g_deg[NN];
__device__ __align__(16) int   g_cursor[NN];
__device__ __align__(16) int   g_off[NN];                  // block-local exclusive scan
__device__ __align__(16) int   g_bsum[NB];                 // per-block sums
__device__ __align__(16) int   g_bpre[NB + 1];             // scanned block prefixes (+total)
__device__ __align__(16) int   g_esrc[NE];                 // CSR: src per (dst-grouped) edge
__device__ __align__(16) float g_enorm[NE];                // per-edge dinv[s]*dinv[d]
__device__ __align__(16) float g_dinv[NN];
__device__ __align__(16) float g_agg1[(size_t)NN * FIN];   // A_norm @ x
__device__ __align__(16) float g_h1  [(size_t)NN * FHID];  // relu(agg1 @ W1 + b1)
__device__ __align__(16) float g_t2  [(size_t)NN * FOUT];  // h1 @ W2 (raw)

// global CSR offset of node i (valid for 0..NN; i==NN gives total)
__device__ __forceinline__ int csr_off(int i) {
    return (i == NN) ? g_bpre[NB] : (g_off[i] + g_bpre[i >> 10]);
}

// ---------------- CSR build --------------------------------------------------
__global__ void k_zero() {
    int i = blockIdx.x * blockDim.x + threadIdx.x;
    if (i < NN) g_deg[i] = 0;
}

__global__ void k_count_deg(const int* __restrict__ dst) {
    int e = blockIdx.x * blockDim.x + threadIdx.x;
    if (e >= NE) return;
    int d = dst[e];
    if ((unsigned)d < (unsigned)NN) atomicAdd(&g_deg[d], 1);
}

// Phase 1: per-block exclusive scan of g_deg -> g_off (block-local),
//          block sums -> g_bsum; ALSO computes g_dinv and zeroes g_cursor.
__global__ __launch_bounds__(1024)
void k_scan1() {
    __shared__ int wsum[32];
    int tid = threadIdx.x, lane = tid & 31, wid = tid >> 5;
    int i = blockIdx.x * 1024 + tid;
    int v = 0;
    if (i < NN) {
        v = g_deg[i];
        g_dinv[i]   = rsqrtf((float)(v + 1));   // +1 self loop
        g_cursor[i] = 0;
    }
    int x = v;
    #pragma unroll
    for (int o = 1; o < 32; o <<= 1) {
        int t = __shfl_up_sync(0xffffffffu, x, o);
        if (lane >= o) x += t;
    }
    if (lane == 31) wsum[wid] = x;
    __syncthreads();
    if (wid == 0) {
        int s = wsum[lane];
        #pragma unroll
        for (int o = 1; o < 32; o <<= 1) {
            int t = __shfl_up_sync(0xffffffffu, s, o);
            if (lane >= o) s += t;
        }
        wsum[lane] = s;              // inclusive scan of warp sums
    }
    __syncthreads();
    int wprefix = (wid == 0) ? 0 : wsum[wid - 1];
    if (i < NN) g_off[i] = wprefix + x - v;     // block-local exclusive
    if (tid == 1023) g_bsum[blockIdx.x] = wsum[31];
}

// Phase 2: scan the 49 block sums (one block, 64 threads)
__global__ void k_scan2() {
    __shared__ int ws[2];
    int tid = threadIdx.x, lane = tid & 31, wid = tid >> 5;
    int v = (tid < NB) ? g_bsum[tid] : 0;
    int x = v;
    #pragma unroll
    for (int o = 1; o < 32; o <<= 1) {
        int t = __shfl_up_sync(0xffffffffu, x, o);
        if (lane >= o) x += t;
    }
    if (lane == 31) ws[wid] = x;
    __syncthreads();
    int pre = (wid == 1) ? ws[0] : 0;
    if (tid < NB) g_bpre[tid] = pre + x - v;    // exclusive
    if (tid == NB - 1) g_bpre[NB] = pre + x;    // total
}

// Fill CSR; precompute per-edge norm = dinv[s]*dinv[d]
__global__ void k_fill(const int* __restrict__ src, const int* __restrict__ dst) {
    int e = blockIdx.x * blockDim.x + threadIdx.x;
    if (e >= NE) return;
    int d = dst[e];
    int s = src[e];
    if ((unsigned)d >= (unsigned)NN || (unsigned)s >= (unsigned)NN) return;
    int pos = csr_off(d) + atomicAdd(&g_cursor[d], 1);
    g_esrc[pos]  = s;
    g_enorm[pos] = g_dinv[s] * g_dinv[d];
}

// ---------------- gather-aggregate (warp per destination) --------------------
// LAYER2=false: g_agg1[d] = xin[d]*dinv[d]^2 + sum_in xin[s]*norm
// LAYER2=true : outp[d]  = relu( g_t2[d]*dinv^2 + sum_in g_t2[s]*norm + bias )
template <bool LAYER2>
__global__ __launch_bounds__(256)
void k_aggr(const float* __restrict__ xin, const float* __restrict__ bias,
            float* __restrict__ outp) {
    const float* __restrict__ feat = LAYER2 ? g_t2 : xin;
    float* __restrict__       dstp = LAYER2 ? outp : g_agg1;

    int gw   = (blockIdx.x * blockDim.x + threadIdx.x) >> 5;   // node
    int lane = threadIdx.x & 31;
    if (gw >= NN) return;
    float dd = g_dinv[gw];
    float s2 = dd * dd;
    float4 a = ((const float4*)(feat + (size_t)gw * 128))[lane];
    float4 acc = make_float4(a.x * s2, a.y * s2, a.z * s2, a.w * s2);

    int i   = csr_off(gw);
    int end = csr_off(gw + 1);
    for (; i + 3 < end; i += 4) {
        int s0 = g_esrc[i],     s1 = g_esrc[i + 1];
        int s2i = g_esrc[i + 2], s3 = g_esrc[i + 3];
        float n0 = g_enorm[i],     n1 = g_enorm[i + 1];
        float n2 = g_enorm[i + 2], n3 = g_enorm[i + 3];
        float4 v0 = ((const float4*)(feat + (size_t)s0 * 128))[lane];
        float4 v1 = ((const float4*)(feat + (size_t)s1 * 128))[lane];
        float4 v2 = ((const float4*)(feat + (size_t)s2i * 128))[lane];
        float4 v3 = ((const float4*)(feat + (size_t)s3 * 128))[lane];
        acc.x += v0.x * n0; acc.y += v0.y * n0; acc.z += v0.z * n0; acc.w += v0.w * n0;
        acc.x += v1.x * n1; acc.y += v1.y * n1; acc.z += v1.z * n1; acc.w += v1.w * n1;
        acc.x += v2.x * n2; acc.y += v2.y * n2; acc.z += v2.z * n2; acc.w += v2.w * n2;
        acc.x += v3.x * n3; acc.y += v3.y * n3; acc.z += v3.z * n3; acc.w += v3.w * n3;
    }
    for (; i < end; i++) {
        int s0 = g_esrc[i];
        float n0 = g_enorm[i];
        float4 v0 = ((const float4*)(feat + (size_t)s0 * 128))[lane];
        acc.x += v0.x * n0; acc.y += v0.y * n0; acc.z += v0.z * n0; acc.w += v0.w * n0;
    }
    if (LAYER2) {
        float4 b = ((const float4*)bias)[lane];
        acc.x = fmaxf(acc.x + b.x, 0.f); acc.y = fmaxf(acc.y + b.y, 0.f);
        acc.z = fmaxf(acc.z + b.z, 0.f); acc.w = fmaxf(acc.w + b.w, 0.f);
    }
    ((float4*)(dstp + (size_t)gw * 128))[lane] = acc;
}

// ---------------- tf32 tensor-core GEMM (register double-buffered) -----------
__device__ __forceinline__ unsigned f2tf(float f) {
    unsigned u;
    asm("cvt.rna.tf32.f32 %0, %1;" : "=r"(u) : "f"(f));
    return u;
}

template <bool LAYER1>
__global__ __launch_bounds__(256)
void mma_gemm(const float* __restrict__ B, const float* __restrict__ bias) {
    constexpr int N  = LAYER1 ? FHID : FOUT;
    constexpr int K  = LAYER1 ? FIN  : FHID;
    constexpr int BM = 128, BK = 16;
    constexpr int APITCH = 20;
    constexpr int BPITCH = 136;
    const float* __restrict__ A = LAYER1 ? g_agg1 : g_h1;
    float* __restrict__       C = LAYER1 ? g_h1   : g_t2;

    __shared__ unsigned As[BM * APITCH];
    __shared__ unsigned Bs[BK * BPITCH];

    int tid  = threadIdx.x;
    int lane = tid & 31;
    int wid  = tid >> 5;
    int warp_m = wid >> 2;
    int warp_n = wid & 3;
    int block_row = blockIdx.y * BM;
    int block_col = blockIdx.x * 128;

    int ar = tid >> 2;
    int aq = (tid & 3) * 4;
    int bkr = tid >> 5;
    int bc  = (tid & 31) * 4;

    auto loadA = [&](int k0, int it) -> float4 {
        int grow = block_row + ar + it * 64;
        if (grow < NN) return *(const float4*)&A[(size_t)grow * K + k0 + aq];
        return make_float4(0.f, 0.f, 0.f, 0.f);
    };
    auto loadB = [&](int k0, int it) -> float4 {
        return *(const float4*)&B[(size_t)(k0 + bkr + it * 8) * N + block_col + bc];
    };

    float acc[4][4][4];
    #pragma unroll
    for (int i = 0; i < 4; i++)
        #pragma unroll
        for (int j = 0; j < 4; j++)
            #pragma unroll
            for (int c = 0; c < 4; c++) acc[i][j][c] = 0.f;

    float4 a_pre[2], b_pre[2];
    a_pre[0] = loadA(0, 0); a_pre[1] = loadA(0, 1);
    b_pre[0] = loadB(0, 0); b_pre[1] = loadB(0, 1);

    for (int k0 = 0; k0 < K; k0 += BK) {
        #pragma unroll
        for (int it = 0; it < 2; it++) {
            unsigned* dp = &As[(ar + it * 64) * APITCH + aq];
            dp[0] = f2tf(a_pre[it].x); dp[1] = f2tf(a_pre[it].y);
            dp[2] = f2tf(a_pre[it].z); dp[3] = f2tf(a_pre[it].w);
            unsigned* bp = &Bs[(bkr + it * 8) * BPITCH + bc];
            bp[0] = f2tf(b_pre[it].x); bp[1] = f2tf(b_pre[it].y);
            bp[2] = f2tf(b_pre[it].z); bp[3] = f2tf(b_pre[it].w);
        }
        __syncthreads();

        if (k0 + BK < K) {
            a_pre[0] = loadA(k0 + BK, 0); a_pre[1] = loadA(k0 + BK, 1);
            b_pre[0] = loadB(k0 + BK, 0); b_pre[1] = loadB(k0 + BK, 1);
        }

        #pragma unroll
        for (int ks = 0; ks < 2; ks++) {
            int kk = ks * 8;
            unsigned af[4][4], bf[4][2];
            #pragma unroll
            for (int mt = 0; mt < 4; mt++) {
                int r = warp_m * 64 + mt * 16 + (lane >> 2);
                int kc = kk + (lane & 3);
                af[mt][0] = As[r * APITCH + kc];
                af[mt][1] = As[(r + 8) * APITCH + kc];
                af[mt][2] = As[r * APITCH + kc + 4];
                af[mt][3] = As[(r + 8) * APITCH + kc + 4];
            }
            #pragma unroll
            for (int nt = 0; nt < 4; nt++) {
                int c = warp_n * 32 + nt * 8 + (lane >> 2);
                bf[nt][0] = Bs[(kk + (lane & 3)) * BPITCH + c];
                bf[nt][1] = Bs[(kk + (lane & 3) + 4) * BPITCH + c];
            }
            #pragma unroll
            for (int mt = 0; mt < 4; mt++)
                #pragma unroll
                for (int nt = 0; nt < 4; nt++)
                    asm volatile(
                        "mma.sync.aligned.m16n8k8.row.col.f32.tf32.tf32.f32 "
                        "{%0,%1,%2,%3}, {%4,%5,%6,%7}, {%8,%9}, {%0,%1,%2,%3};"
                        : "+f"(acc[mt][nt][0]), "+f"(acc[mt][nt][1]),
                          "+f"(acc[mt][nt][2]), "+f"(acc[mt][nt][3])
                        : "r"(af[mt][0]), "r"(af[mt][1]),
                          "r"(af[mt][2]), "r"(af[mt][3]),
                          "r"(bf[nt][0]), "r"(bf[nt][1]));
        }
        __syncthreads();
    }

    #pragma unroll
    for (int mt = 0; mt < 4; mt++) {
        int r0 = block_row + warp_m * 64 + mt * 16 + (lane >> 2);
        #pragma unroll
        for (int half = 0; half < 2; half++) {
            int row = r0 + half * 8;
            if (row >= NN) continue;
            #pragma unroll
            for (int nt = 0; nt < 4; nt++) {
                int col = block_col + warp_n * 32 + nt * 8 + (lane & 3) * 2;
                float v0 = acc[mt][nt][half * 2 + 0];
                float v1 = acc[mt][nt][half * 2 + 1];
                if (LAYER1) {
                    v0 = fmaxf(v0 + bias[col],     0.f);
                    v1 = fmaxf(v1 + bias[col + 1], 0.f);
                }
                *(float2*)&C[(size_t)row * N + col] = make_float2(v0, v1);
            }
        }
    }
}

// ---------------- launch ------------------------------------------------------
extern "C" void kernel_launch(void* const* d_in, const int* in_sizes, int n_in,
                              void* d_out, int out_size) {
    const float* x  = (const float*)d_in[0];
    const int*   ei = (const int*)d_in[1];    // int32 (JAX x64 disabled)
    const float* W1 = (const float*)d_in[2];
    const float* b1 = (const float*)d_in[3];
    const float* W2 = (const float*)d_in[4];
    const float* b2 = (const float*)d_in[5];
    float* out = (float*)d_out;

    const int* srcp = ei;        // edge_index[0]
    const int* dstp = ei + NE;   // edge_index[1]

    const int T = 256;
    const int MBLK = (NN + 127) / 128;   // 391
    const int AGGR_GRID = (NN * 32 + T - 1) / T;

    // CSR build (scan1 folds in dinv + cursor init; consumers add block prefix)
    k_zero     <<<(NN + T - 1) / T, T>>>();                 // 1
    k_count_deg<<<(NE + T - 1) / T, T>>>(dstp);             // 2
    k_scan1    <<<NB, 1024>>>();                            // 3
    k_scan2    <<<1, 64>>>();                               // 4
    k_fill     <<<(NE + T - 1) / T, T>>>(srcp, dstp);       // 5

    // layer 1: agg1 = A_norm @ x ; h1 = relu(agg1 @ W1 + b1)
    k_aggr<false><<<AGGR_GRID, T>>>(x, nullptr, nullptr);   // 6  <- ncu profiles this
    {
        dim3 grid(FHID / 128, MBLK);
        mma_gemm<true><<<grid, 256>>>(W1, b1);              // 7
    }

    // layer 2: t2 = h1 @ W2 ; out = relu(A_norm @ t2 + b2)
    {
        dim3 grid(FOUT / 128, MBLK);
        mma_gemm<false><<<grid, 256>>>(W2, nullptr);        // 8
    }
    k_aggr<true><<<AGGR_GRID, T>>>(nullptr, b2, out);       // 9
}

// round 10
// speedup vs baseline: 1.0275x; 1.0275x over previous
#include <cuda_runtime.h>
#include <cuda_bf16.h>
#include <cstdint>

// Problem constants
constexpr int NN   = 50000;   // nodes
constexpr int NE   = 800000;  // edges
constexpr int FIN  = 128;
constexpr int FHID = 256;
constexpr int FOUT = 128;
constexpr int NB   = (NN + 1023) / 1024;   // scan blocks = 49

// ---------------- scratch (__device__ globals; referenced ONLY in device code)
__device__ __align__(16) int   g_deg[NN];
__device__ __align__(16) int   g_cursor[NN];
__device__ __align__(16) int   g_off[NN];                  // block-local exclusive scan
__device__ __align__(16) int   g_bsum[NB];                 // per-block sums
__device__ __align__(16) int   g_bpre[NB + 1];             // scanned block prefixes (+total)
__device__ __align__(16) int   g_esrc[NE];                 // CSR: src per (dst-grouped) edge
__device__ __align__(16) float g_dinv[NN];
__device__ __align__(16) __nv_bfloat16 g_xbf[(size_t)NN * FIN];   // bf16 copy of x
__device__ __align__(16) __nv_bfloat16 g_t2b[(size_t)NN * FOUT];  // bf16 h1@W2
__device__ __align__(16) float g_agg1[(size_t)NN * FIN];   // A_norm @ x
__device__ __align__(16) float g_h1  [(size_t)NN * FHID];  // relu(agg1 @ W1 + b1)

// global CSR offset of node i (valid for 0..NN; i==NN gives total)
__device__ __forceinline__ int csr_off(int i) {
    return (i == NN) ? g_bpre[NB] : (g_off[i] + g_bpre[i >> 10]);
}

// ---------------- CSR build --------------------------------------------------
__global__ void k_zero() {
    int i = blockIdx.x * blockDim.x + threadIdx.x;
    if (i < NN) g_deg[i] = 0;
}

__global__ void k_count_deg(const int* __restrict__ dst) {
    int e = blockIdx.x * blockDim.x + threadIdx.x;
    if (e >= NE) return;
    int d = dst[e];
    if ((unsigned)d < (unsigned)NN) atomicAdd(&g_deg[d], 1);
}

// Phase 1: per-block exclusive scan of g_deg -> g_off (block-local),
//          block sums -> g_bsum; ALSO computes g_dinv and zeroes g_cursor.
__global__ __launch_bounds__(1024)
void k_scan1() {
    __shared__ int wsum[32];
    int tid = threadIdx.x, lane = tid & 31, wid = tid >> 5;
    int i = blockIdx.x * 1024 + tid;
    int v = 0;
    if (i < NN) {
        v = g_deg[i];
        g_dinv[i]   = rsqrtf((float)(v + 1));   // +1 self loop
        g_cursor[i] = 0;
    }
    int x = v;
    #pragma unroll
    for (int o = 1; o < 32; o <<= 1) {
        int t = __shfl_up_sync(0xffffffffu, x, o);
        if (lane >= o) x += t;
    }
    if (lane == 31) wsum[wid] = x;
    __syncthreads();
    if (wid == 0) {
        int s = wsum[lane];
        #pragma unroll
        for (int o = 1; o < 32; o <<= 1) {
            int t = __shfl_up_sync(0xffffffffu, s, o);
            if (lane >= o) s += t;
        }
        wsum[lane] = s;              // inclusive scan of warp sums
    }
    __syncthreads();
    int wprefix = (wid == 0) ? 0 : wsum[wid - 1];
    if (i < NN) g_off[i] = wprefix + x - v;     // block-local exclusive
    if (tid == 1023) g_bsum[blockIdx.x] = wsum[31];
}

// Phase 2: scan the 49 block sums (one block, 64 threads)
__global__ void k_scan2() {
    __shared__ int ws[2];
    int tid = threadIdx.x, lane = tid & 31, wid = tid >> 5;
    int v = (tid < NB) ? g_bsum[tid] : 0;
    int x = v;
    #pragma unroll
    for (int o = 1; o < 32; o <<= 1) {
        int t = __shfl_up_sync(0xffffffffu, x, o);
        if (lane >= o) x += t;
    }
    if (lane == 31) ws[wid] = x;
    __syncthreads();
    int pre = (wid == 1) ? ws[0] : 0;
    if (tid < NB) g_bpre[tid] = pre + x - v;    // exclusive
    if (tid == NB - 1) g_bpre[NB] = pre + x;    // total
}

// Fill CSR (src only; norm recomputed from cached dinv in aggregate)
__global__ void k_fill(const int* __restrict__ src, const int* __restrict__ dst) {
    int e = blockIdx.x * blockDim.x + threadIdx.x;
    if (e >= NE) return;
    int d = dst[e];
    int s = src[e];
    if ((unsigned)d >= (unsigned)NN || (unsigned)s >= (unsigned)NN) return;
    int pos = csr_off(d) + atomicAdd(&g_cursor[d], 1);
    g_esrc[pos] = s;
}

// Convert x (fp32) -> g_xbf (bf16); 4 elems/thread
__global__ void k_cvt_x(const float* __restrict__ x) {
    int idx = blockIdx.x * blockDim.x + threadIdx.x;   // over NN*FIN/4
    if (idx >= NN * (FIN / 4)) return;
    float4 v = ((const float4*)x)[idx];
    __nv_bfloat162 lo = __float22bfloat162_rn(make_float2(v.x, v.y));
    __nv_bfloat162 hi = __float22bfloat162_rn(make_float2(v.z, v.w));
    ((__nv_bfloat162*)g_xbf)[idx * 2 + 0] = lo;
    ((__nv_bfloat162*)g_xbf)[idx * 2 + 1] = hi;
}

// ---------------- gather-aggregate (warp per destination, bf16 features) -----
// LAYER2=false: g_agg1[d] = xbf[d]*dinv^2 + sum_in xbf[s]*dinv[s]dinv[d]   (fp32 out)
// LAYER2=true : outp[d]  = relu( t2b[d]*dinv^2 + sum_in t2b[s]*... + bias ) (fp32 out)
// feature row = 128 bf16 = 256B; lane handles feats [4*lane .. 4*lane+3] (8B load)
template <bool LAYER2>
__global__ __launch_bounds__(256)
void k_aggr(const float* __restrict__ bias, float* __restrict__ outp) {
    const __nv_bfloat16* __restrict__ feat = LAYER2 ? g_t2b : g_xbf;
    float* __restrict__ dstp = LAYER2 ? outp : g_agg1;

    int gw   = (blockIdx.x * blockDim.x + threadIdx.x) >> 5;   // node
    int lane = threadIdx.x & 31;
    if (gw >= NN) return;
    float dd = g_dinv[gw];
    float s2 = dd * dd;

    auto loadrow = [&](int node) -> float4 {
        uint2 u = ((const uint2*)(feat + (size_t)node * 128))[lane];
        float2 lo = __bfloat1622float2(*(const __nv_bfloat162*)&u.x);
        float2 hi = __bfloat1622float2(*(const __nv_bfloat162*)&u.y);
        return make_float4(lo.x, lo.y, hi.x, hi.y);
    };

    float4 a = loadrow(gw);
    float4 acc = make_float4(a.x * s2, a.y * s2, a.z * s2, a.w * s2);

    int i   = csr_off(gw);
    int end = csr_off(gw + 1);
    for (; i + 3 < end; i += 4) {
        int s0 = g_esrc[i],      s1 = g_esrc[i + 1];
        int s2i = g_esrc[i + 2], s3 = g_esrc[i + 3];
        float n0 = g_dinv[s0] * dd,  n1 = g_dinv[s1] * dd;
        float n2 = g_dinv[s2i] * dd, n3 = g_dinv[s3] * dd;
        float4 v0 = loadrow(s0);
        float4 v1 = loadrow(s1);
        float4 v2 = loadrow(s2i);
        float4 v3 = loadrow(s3);
        acc.x += v0.x * n0; acc.y += v0.y * n0; acc.z += v0.z * n0; acc.w += v0.w * n0;
        acc.x += v1.x * n1; acc.y += v1.y * n1; acc.z += v1.z * n1; acc.w += v1.w * n1;
        acc.x += v2.x * n2; acc.y += v2.y * n2; acc.z += v2.z * n2; acc.w += v2.w * n2;
        acc.x += v3.x * n3; acc.y += v3.y * n3; acc.z += v3.z * n3; acc.w += v3.w * n3;
    }
    for (; i < end; i++) {
        int s0 = g_esrc[i];
        float n0 = g_dinv[s0] * dd;
        float4 v0 = loadrow(s0);
        acc.x += v0.x * n0; acc.y += v0.y * n0; acc.z += v0.z * n0; acc.w += v0.w * n0;
    }
    if (LAYER2) {
        float4 b = ((const float4*)bias)[lane];
        acc.x = fmaxf(acc.x + b.x, 0.f); acc.y = fmaxf(acc.y + b.y, 0.f);
        acc.z = fmaxf(acc.z + b.z, 0.f); acc.w = fmaxf(acc.w + b.w, 0.f);
    }
    ((float4*)(dstp + (size_t)gw * 128))[lane] = acc;
}

// ---------------- tf32 tensor-core GEMM (register double-buffered) -----------
// LAYER1: g_h1 (fp32) = relu(g_agg1[NN,128] @ W1 + b1)
// LAYER2: g_t2b (bf16) = g_h1[NN,256] @ W2
__device__ __forceinline__ unsigned f2tf(float f) {
    unsigned u;
    asm("cvt.rna.tf32.f32 %0, %1;" : "=r"(u) : "f"(f));
    return u;
}

template <bool LAYER1>
__global__ __launch_bounds__(256)
void mma_gemm(const float* __restrict__ B, const float* __restrict__ bias) {
    constexpr int N  = LAYER1 ? FHID : FOUT;
    constexpr int K  = LAYER1 ? FIN  : FHID;
    constexpr int BM = 128, BK = 16;
    constexpr int APITCH = 20;
    constexpr int BPITCH = 136;
    const float* __restrict__ A = LAYER1 ? g_agg1 : g_h1;

    __shared__ unsigned As[BM * APITCH];
    __shared__ unsigned Bs[BK * BPITCH];

    int tid  = threadIdx.x;
    int lane = tid & 31;
    int wid  = tid >> 5;
    int warp_m = wid >> 2;
    int warp_n = wid & 3;
    int block_row = blockIdx.y * BM;
    int block_col = blockIdx.x * 128;

    int ar = tid >> 2;
    int aq = (tid & 3) * 4;
    int bkr = tid >> 5;
    int bc  = (tid & 31) * 4;

    auto loadA = [&](int k0, int it) -> float4 {
        int grow = block_row + ar + it * 64;
        if (grow < NN) return *(const float4*)&A[(size_t)grow * K + k0 + aq];
        return make_float4(0.f, 0.f, 0.f, 0.f);
    };
    auto loadB = [&](int k0, int it) -> float4 {
        return *(const float4*)&B[(size_t)(k0 + bkr + it * 8) * N + block_col + bc];
    };

    float acc[4][4][4];
    #pragma unroll
    for (int i = 0; i < 4; i++)
        #pragma unroll
        for (int j = 0; j < 4; j++)
            #pragma unroll
            for (int c = 0; c < 4; c++) acc[i][j][c] = 0.f;

    float4 a_pre[2], b_pre[2];
    a_pre[0] = loadA(0, 0); a_pre[1] = loadA(0, 1);
    b_pre[0] = loadB(0, 0); b_pre[1] = loadB(0, 1);

    for (int k0 = 0; k0 < K; k0 += BK) {
        #pragma unroll
        for (int it = 0; it < 2; it++) {
            unsigned* dp = &As[(ar + it * 64) * APITCH + aq];
            dp[0] = f2tf(a_pre[it].x); dp[1] = f2tf(a_pre[it].y);
            dp[2] = f2tf(a_pre[it].z); dp[3] = f2tf(a_pre[it].w);
            unsigned* bp = &Bs[(bkr + it * 8) * BPITCH + bc];
            bp[0] = f2tf(b_pre[it].x); bp[1] = f2tf(b_pre[it].y);
            bp[2] = f2tf(b_pre[it].z); bp[3] = f2tf(b_pre[it].w);
        }
        __syncthreads();

        if (k0 + BK < K) {
            a_pre[0] = loadA(k0 + BK, 0); a_pre[1] = loadA(k0 + BK, 1);
            b_pre[0] = loadB(k0 + BK, 0); b_pre[1] = loadB(k0 + BK, 1);
        }

        #pragma unroll
        for (int ks = 0; ks < 2; ks++) {
            int kk = ks * 8;
            unsigned af[4][4], bf[4][2];
            #pragma unroll
            for (int mt = 0; mt < 4; mt++) {
                int r = warp_m * 64 + mt * 16 + (lane >> 2);
                int kc = kk + (lane & 3);
                af[mt][0] = As[r * APITCH + kc];
                af[mt][1] = As[(r + 8) * APITCH + kc];
                af[mt][2] = As[r * APITCH + kc + 4];
                af[mt][3] = As[(r + 8) * APITCH + kc + 4];
            }
            #pragma unroll
            for (int nt = 0; nt < 4; nt++) {
                int c = warp_n * 32 + nt * 8 + (lane >> 2);
                bf[nt][0] = Bs[(kk + (lane & 3)) * BPITCH + c];
                bf[nt][1] = Bs[(kk + (lane & 3) + 4) * BPITCH + c];
            }
            #pragma unroll
            for (int mt = 0; mt < 4; mt++)
                #pragma unroll
                for (int nt = 0; nt < 4; nt++)
                    asm volatile(
                        "mma.sync.aligned.m16n8k8.row.col.f32.tf32.tf32.f32 "
                        "{%0,%1,%2,%3}, {%4,%5,%6,%7}, {%8,%9}, {%0,%1,%2,%3};"
                        : "+f"(acc[mt][nt][0]), "+f"(acc[mt][nt][1]),
                          "+f"(acc[mt][nt][2]), "+f"(acc[mt][nt][3])
                        : "r"(af[mt][0]), "r"(af[mt][1]),
                          "r"(af[mt][2]), "r"(af[mt][3]),
                          "r"(bf[nt][0]), "r"(bf[nt][1]));
        }
        __syncthreads();
    }

    #pragma unroll
    for (int mt = 0; mt < 4; mt++) {
        int r0 = block_row + warp_m * 64 + mt * 16 + (lane >> 2);
        #pragma unroll
        for (int half = 0; half < 2; half++) {
            int row = r0 + half * 8;
            if (row >= NN) continue;
            #pragma unroll
            for (int nt = 0; nt < 4; nt++) {
                int col = block_col + warp_n * 32 + nt * 8 + (lane & 3) * 2;
                float v0 = acc[mt][nt][half * 2 + 0];
                float v1 = acc[mt][nt][half * 2 + 1];
                if (LAYER1) {
                    v0 = fmaxf(v0 + bias[col],     0.f);
                    v1 = fmaxf(v1 + bias[col + 1], 0.f);
                    *(float2*)&g_h1[(size_t)row * N + col] = make_float2(v0, v1);
                } else {
                    __nv_bfloat162 p = __float22bfloat162_rn(make_float2(v0, v1));
                    *(__nv_bfloat162*)&g_t2b[(size_t)row * N + col] = p;
                }
            }
        }
    }
}

// ---------------- launch ------------------------------------------------------
extern "C" void kernel_launch(void* const* d_in, const int* in_sizes, int n_in,
                              void* d_out, int out_size) {
    const float* x  = (const float*)d_in[0];
    const int*   ei = (const int*)d_in[1];    // int32 (JAX x64 disabled)
    const float* W1 = (const float*)d_in[2];
    const float* b1 = (const float*)d_in[3];
    const float* W2 = (const float*)d_in[4];
    const float* b2 = (const float*)d_in[5];
    float* out = (float*)d_out;

    const int* srcp = ei;        // edge_index[0]
    const int* dstp = ei + NE;   // edge_index[1]

    const int T = 256;
    const int MBLK = (NN + 127) / 128;   // 391
    const int AGGR_GRID = (NN * 32 + T - 1) / T;

    // CSR build + bf16 convert
    k_zero     <<<(NN + T - 1) / T, T>>>();
    k_count_deg<<<(NE + T - 1) / T, T>>>(dstp);
    k_scan1    <<<NB, 1024>>>();
    k_scan2    <<<1, 64>>>();
    k_fill     <<<(NE + T - 1) / T, T>>>(srcp, dstp);
    k_cvt_x    <<<(NN * (FIN/4) + T - 1) / T, T>>>(x);

    // layer 1: agg1 = A_norm @ x ; h1 = relu(agg1 @ W1 + b1)
    k_aggr<false><<<AGGR_GRID, T>>>(nullptr, nullptr);
    {
        dim3 grid(FHID / 128, MBLK);
        mma_gemm<true><<<grid, 256>>>(W1, b1);
    }

    // layer 2: t2b = bf16(h1 @ W2) ; out = relu(A_norm @ t2b + b2)
    {
        dim3 grid(FOUT / 128, MBLK);
        mma_gemm<false><<<grid, 256>>>(W2, nullptr);
    }
    k_aggr<true><<<AGGR_GRID, T>>>(b2, out);
}

// round 12
// speedup vs baseline: 1.0499x; 1.0218x over previous
#include <cuda_runtime.h>
#include <cstdint>

// Problem constants
constexpr int NN   = 50000;   // nodes
constexpr int NE   = 800000;  // edges
constexpr int FIN  = 128;
constexpr int FHID = 256;
constexpr int FOUT = 128;
constexpr int NB   = (NN + 1023) / 1024;   // scan blocks = 49

// ---------------- scratch (__device__ globals; referenced ONLY in device code)
// g_deg: zero at module load (BSS); re-zeroed at the END of each call by
// k_aggr<true>, so every call sees g_deg == 0 deterministically.
__device__ __align__(16) int   g_deg[NN];
__device__ __align__(16) int   g_cursor[NN];
__device__ __align__(16) int   g_off[NN];                  // block-local exclusive scan
__device__ __align__(16) int   g_bsum[NB];                 // per-block sums
__device__ __align__(16) int   g_bpre[NB + 1];             // scanned block prefixes (+total)
__device__ __align__(16) int   g_esrc[NE];                 // CSR: src per (dst-grouped) edge
__device__ __align__(16) float g_dinv[NN];
__device__ __align__(16) float g_agg1[(size_t)NN * FIN];   // A_norm @ x
__device__ __align__(16) float g_h1  [(size_t)NN * FHID];  // relu(agg1 @ W1 + b1)
__device__ __align__(16) float g_t2  [(size_t)NN * FOUT];  // h1 @ W2 (raw)

// global CSR offset of node i (valid for 0..NN; i==NN gives total)
__device__ __forceinline__ int csr_off(int i) {
    return (i == NN) ? g_bpre[NB] : (g_off[i] + g_bpre[i >> 10]);
}

// ---------------- CSR build --------------------------------------------------
__global__ void k_count_deg(const int* __restrict__ dst) {
    int e = blockIdx.x * blockDim.x + threadIdx.x;
    if (e >= NE) return;
    int d = dst[e];
    if ((unsigned)d < (unsigned)NN) atomicAdd(&g_deg[d], 1);
}

// Phase 1: per-block exclusive scan of g_deg -> g_off (block-local),
//          block sums -> g_bsum; ALSO computes g_dinv and zeroes g_cursor.
__global__ __launch_bounds__(1024)
void k_scan1() {
    __shared__ int wsum[32];
    int tid = threadIdx.x, lane = tid & 31, wid = tid >> 5;
    int i = blockIdx.x * 1024 + tid;
    int v = 0;
    if (i < NN) {
        v = g_deg[i];
        g_dinv[i]   = rsqrtf((float)(v + 1));   // +1 self loop
        g_cursor[i] = 0;
    }
    int x = v;
    #pragma unroll
    for (int o = 1; o < 32; o <<= 1) {
        int t = __shfl_up_sync(0xffffffffu, x, o);
        if (lane >= o) x += t;
    }
    if (lane == 31) wsum[wid] = x;
    __syncthreads();
    if (wid == 0) {
        int s = wsum[lane];
        #pragma unroll
        for (int o = 1; o < 32; o <<= 1) {
            int t = __shfl_up_sync(0xffffffffu, s, o);
            if (lane >= o) s += t;
        }
        wsum[lane] = s;              // inclusive scan of warp sums
    }
    __syncthreads();
    int wprefix = (wid == 0) ? 0 : wsum[wid - 1];
    if (i < NN) g_off[i] = wprefix + x - v;     // block-local exclusive
    if (tid == 1023) g_bsum[blockIdx.x] = wsum[31];
}

// Phase 2: scan the 49 block sums (one block, 64 threads)
__global__ void k_scan2() {
    __shared__ int ws[2];
    int tid = threadIdx.x, lane = tid & 31, wid = tid >> 5;
    int v = (tid < NB) ? g_bsum[tid] : 0;
    int x = v;
    #pragma unroll
    for (int o = 1; o < 32; o <<= 1) {
        int t = __shfl_up_sync(0xffffffffu, x, o);
        if (lane >= o) x += t;
    }
    if (lane == 31) ws[wid] = x;
    __syncthreads();
    int pre = (wid == 1) ? ws[0] : 0;
    if (tid < NB) g_bpre[tid] = pre + x - v;    // exclusive
    if (tid == NB - 1) g_bpre[NB] = pre + x;    // total
}

// Fill CSR (src only; norm recomputed from cached dinv in aggregate)
__global__ void k_fill(const int* __restrict__ src, const int* __restrict__ dst) {
    int e = blockIdx.x * blockDim.x + threadIdx.x;
    if (e >= NE) return;
    int d = dst[e];
    int s = src[e];
    if ((unsigned)d >= (unsigned)NN || (unsigned)s >= (unsigned)NN) return;
    int pos = csr_off(d) + atomicAdd(&g_cursor[d], 1);
    g_esrc[pos] = s;
}

// ---------------- gather-aggregate (warp per destination, fp32) --------------
// LAYER2=false: g_agg1[d] = xin[d]*dinv^2 + sum_in xin[s]*dinv[s]dinv[d]
// LAYER2=true : outp[d]  = relu( g_t2[d]*dinv^2 + sum_in g_t2[s]*... + bias )
//               ALSO re-zeroes g_deg for the next call (deterministic).
template <bool LAYER2>
__global__ __launch_bounds__(256)
void k_aggr(const float* __restrict__ xin, const float* __restrict__ bias,
            float* __restrict__ outp) {
    const float* __restrict__ feat = LAYER2 ? g_t2 : xin;
    float* __restrict__       dstp = LAYER2 ? outp : g_agg1;

    int gtid = blockIdx.x * blockDim.x + threadIdx.x;
    if (LAYER2) {
        // reset degree array for the next kernel_launch call
        if (gtid < NN) g_deg[gtid] = 0;
    }

    int gw   = gtid >> 5;                      // node
    int lane = threadIdx.x & 31;
    if (gw >= NN) return;
    float dd = g_dinv[gw];
    float s2 = dd * dd;
    float4 a = ((const float4*)(feat + (size_t)gw * 128))[lane];
    float4 acc = make_float4(a.x * s2, a.y * s2, a.z * s2, a.w * s2);

    int i   = csr_off(gw);
    int end = csr_off(gw + 1);
    for (; i + 3 < end; i += 4) {
        int s0 = g_esrc[i],      s1 = g_esrc[i + 1];
        int s2i = g_esrc[i + 2], s3 = g_esrc[i + 3];
        float n0 = g_dinv[s0] * dd,  n1 = g_dinv[s1] * dd;
        float n2 = g_dinv[s2i] * dd, n3 = g_dinv[s3] * dd;
        float4 v0 = ((const float4*)(feat + (size_t)s0 * 128))[lane];
        float4 v1 = ((const float4*)(feat + (size_t)s1 * 128))[lane];
        float4 v2 = ((const float4*)(feat + (size_t)s2i * 128))[lane];
        float4 v3 = ((const float4*)(feat + (size_t)s3 * 128))[lane];
        acc.x += v0.x * n0; acc.y += v0.y * n0; acc.z += v0.z * n0; acc.w += v0.w * n0;
        acc.x += v1.x * n1; acc.y += v1.y * n1; acc.z += v1.z * n1; acc.w += v1.w * n1;
        acc.x += v2.x * n2; acc.y += v2.y * n2; acc.z += v2.z * n2; acc.w += v2.w * n2;
        acc.x += v3.x * n3; acc.y += v3.y * n3; acc.z += v3.z * n3; acc.w += v3.w * n3;
    }
    for (; i < end; i++) {
        int s0 = g_esrc[i];
        float n0 = g_dinv[s0] * dd;
        float4 v0 = ((const float4*)(feat + (size_t)s0 * 128))[lane];
        acc.x += v0.x * n0; acc.y += v0.y * n0; acc.z += v0.z * n0; acc.w += v0.w * n0;
    }
    if (LAYER2) {
        float4 b = ((const float4*)bias)[lane];
        acc.x = fmaxf(acc.x + b.x, 0.f); acc.y = fmaxf(acc.y + b.y, 0.f);
        acc.z = fmaxf(acc.z + b.z, 0.f); acc.w = fmaxf(acc.w + b.w, 0.f);
    }
    ((float4*)(dstp + (size_t)gw * 128))[lane] = acc;
}

// ---------------- tf32 tensor-core GEMM (register double-buffered) -----------
__device__ __forceinline__ unsigned f2tf(float f) {
    unsigned u;
    asm("cvt.rna.tf32.f32 %0, %1;" : "=r"(u) : "f"(f));
    return u;
}

template <bool LAYER1>
__global__ __launch_bounds__(256)
void mma_gemm(const float* __restrict__ B, const float* __restrict__ bias) {
    constexpr int N  = LAYER1 ? FHID : FOUT;
    constexpr int K  = LAYER1 ? FIN  : FHID;
    constexpr int BM = 128, BK = 16;
    constexpr int APITCH = 20;
    constexpr int BPITCH = 136;
    const float* __restrict__ A = LAYER1 ? g_agg1 : g_h1;
    float* __restrict__       C = LAYER1 ? g_h1   : g_t2;

    __shared__ unsigned As[BM * APITCH];
    __shared__ unsigned Bs[BK * BPITCH];

    int tid  = threadIdx.x;
    int lane = tid & 31;
    int wid  = tid >> 5;
    int warp_m = wid >> 2;
    int warp_n = wid & 3;
    int block_row = blockIdx.y * BM;
    int block_col = blockIdx.x * 128;

    int ar = tid >> 2;
    int aq = (tid & 3) * 4;
    int bkr = tid >> 5;
    int bc  = (tid & 31) * 4;

    auto loadA = [&](int k0, int it) -> float4 {
        int grow = block_row + ar + it * 64;
        if (grow < NN) return *(const float4*)&A[(size_t)grow * K + k0 + aq];
        return make_float4(0.f, 0.f, 0.f, 0.f);
    };
    auto loadB = [&](int k0, int it) -> float4 {
        return *(const float4*)&B[(size_t)(k0 + bkr + it * 8) * N + block_col + bc];
    };

    float acc[4][4][4];
    #pragma unroll
    for (int i = 0; i < 4; i++)
        #pragma unroll
        for (int j = 0; j < 4; j++)
            #pragma unroll
            for (int c = 0; c < 4; c++) acc[i][j][c] = 0.f;

    float4 a_pre[2], b_pre[2];
    a_pre[0] = loadA(0, 0); a_pre[1] = loadA(0, 1);
    b_pre[0] = loadB(0, 0); b_pre[1] = loadB(0, 1);

    for (int k0 = 0; k0 < K; k0 += BK) {
        #pragma unroll
        for (int it = 0; it < 2; it++) {
            unsigned* dp = &As[(ar + it * 64) * APITCH + aq];
            dp[0] = f2tf(a_pre[it].x); dp[1] = f2tf(a_pre[it].y);
            dp[2] = f2tf(a_pre[it].z); dp[3] = f2tf(a_pre[it].w);
            unsigned* bp = &Bs[(bkr + it * 8) * BPITCH + bc];
            bp[0] = f2tf(b_pre[it].x); bp[1] = f2tf(b_pre[it].y);
            bp[2] = f2tf(b_pre[it].z); bp[3] = f2tf(b_pre[it].w);
        }
        __syncthreads();

        if (k0 + BK < K) {
            a_pre[0] = loadA(k0 + BK, 0); a_pre[1] = loadA(k0 + BK, 1);
            b_pre[0] = loadB(k0 + BK, 0); b_pre[1] = loadB(k0 + BK, 1);
        }

        #pragma unroll
        for (int ks = 0; ks < 2; ks++) {
            int kk = ks * 8;
            unsigned af[4][4], bf[4][2];
            #pragma unroll
            for (int mt = 0; mt < 4; mt++) {
                int r = warp_m * 64 + mt * 16 + (lane >> 2);
                int kc = kk + (lane & 3);
                af[mt][0] = As[r * APITCH + kc];
                af[mt][1] = As[(r + 8) * APITCH + kc];
                af[mt][2] = As[r * APITCH + kc + 4];
                af[mt][3] = As[(r + 8) * APITCH + kc + 4];
            }
            #pragma unroll
            for (int nt = 0; nt < 4; nt++) {
                int c = warp_n * 32 + nt * 8 + (lane >> 2);
                bf[nt][0] = Bs[(kk + (lane & 3)) * BPITCH + c];
                bf[nt][1] = Bs[(kk + (lane & 3) + 4) * BPITCH + c];
            }
            #pragma unroll
            for (int mt = 0; mt < 4; mt++)
                #pragma unroll
                for (int nt = 0; nt < 4; nt++)
                    asm volatile(
                        "mma.sync.aligned.m16n8k8.row.col.f32.tf32.tf32.f32 "
                        "{%0,%1,%2,%3}, {%4,%5,%6,%7}, {%8,%9}, {%0,%1,%2,%3};"
                        : "+f"(acc[mt][nt][0]), "+f"(acc[mt][nt][1]),
                          "+f"(acc[mt][nt][2]), "+f"(acc[mt][nt][3])
                        : "r"(af[mt][0]), "r"(af[mt][1]),
                          "r"(af[mt][2]), "r"(af[mt][3]),
                          "r"(bf[nt][0]), "r"(bf[nt][1]));
        }
        __syncthreads();
    }

    #pragma unroll
    for (int mt = 0; mt < 4; mt++) {
        int r0 = block_row + warp_m * 64 + mt * 16 + (lane >> 2);
        #pragma unroll
        for (int half = 0; half < 2; half++) {
            int row = r0 + half * 8;
            if (row >= NN) continue;
            #pragma unroll
            for (int nt = 0; nt < 4; nt++) {
                int col = block_col + warp_n * 32 + nt * 8 + (lane & 3) * 2;
                float v0 = acc[mt][nt][half * 2 + 0];
                float v1 = acc[mt][nt][half * 2 + 1];
                if (LAYER1) {
                    v0 = fmaxf(v0 + bias[col],     0.f);
                    v1 = fmaxf(v1 + bias[col + 1], 0.f);
                }
                *(float2*)&C[(size_t)row * N + col] = make_float2(v0, v1);
            }
        }
    }
}

// ---------------- launch ------------------------------------------------------
extern "C" void kernel_launch(void* const* d_in, const int* in_sizes, int n_in,
                              void* d_out, int out_size) {
    const float* x  = (const float*)d_in[0];
    const int*   ei = (const int*)d_in[1];    // int32 (JAX x64 disabled)
    const float* W1 = (const float*)d_in[2];
    const float* b1 = (const float*)d_in[3];
    const float* W2 = (const float*)d_in[4];
    const float* b2 = (const float*)d_in[5];
    float* out = (float*)d_out;

    const int* srcp = ei;        // edge_index[0]
    const int* dstp = ei + NE;   // edge_index[1]

    const int T = 256;
    const int MBLK = (NN + 127) / 128;   // 391
    const int AGGR_GRID = (NN * 32 + T - 1) / T;

    // CSR build (g_deg arrives zeroed: BSS init on first call,
    // re-zeroed by k_aggr<true> at the end of every call)
    k_count_deg<<<(NE + T - 1) / T, T>>>(dstp);             // 1
    k_scan1    <<<NB, 1024>>>();                            // 2
    k_scan2    <<<1, 64>>>();                               // 3
    k_fill     <<<(NE + T - 1) / T, T>>>(srcp, dstp);       // 4  <- profiled
    // layer 1
    k_aggr<false><<<AGGR_GRID, T>>>(x, nullptr, nullptr);   // 5
    {
        dim3 grid(FHID / 128, MBLK);
        mma_gemm<true><<<grid, 256>>>(W1, b1);              // 6
    }
    // layer 2
    {
        dim3 grid(FOUT / 128, MBLK);
        mma_gemm<false><<<grid, 256>>>(W2, nullptr);        // 7
    }
    k_aggr<true><<<AGGR_GRID, T>>>(nullptr, b2, out);       // 8
}